// round 9
// baseline (speedup 1.0000x reference)
#include <cuda_runtime.h>
#include <math.h>

#define B_DIM 64
#define N_DIM 4096
#define K_DIM 32
#define U_DIM 16
#define NUM_STEPS 8
#define BN (B_DIM * N_DIM)            // 262144 sites
#define NU (N_DIM * U_DIM)            // 65536 (GEMM K)
#define H1 256
#define H2 32
#define NCLS 2
#define ROWLEN (K_DIM + 2)            // 34

#define NSPLIT 256
#define KCHUNK (NU / NSPLIT)          // 256

// scratch (device globals: allocation-free)
__device__ float g_h[BN * U_DIM];               // 16 MB: h outputs (B, N*U) row-major
__device__ float g_part[NSPLIT * B_DIM * H1];   // 16 MB: split-K partials

typedef unsigned long long u64;

// ---- f32x2 packed helpers (componentwise fp32: bit-identical to scalar) ----
__device__ __forceinline__ u64 pk2(float lo, float hi) {
    u64 r;
    asm("mov.b64 %0, {%1, %2};" : "=l"(r) : "f"(lo), "f"(hi));
    return r;
}
__device__ __forceinline__ void upk2(float& lo, float& hi, u64 v) {
    asm("mov.b64 {%0, %1}, %2;" : "=f"(lo), "=f"(hi) : "l"(v));
}
__device__ __forceinline__ u64 ffma2(u64 a, u64 b, u64 c) {
    u64 d;
    asm("fma.rn.f32x2 %0, %1, %2, %3;" : "=l"(d) : "l"(a), "l"(b), "l"(c));
    return d;
}

__device__ __forceinline__ float sigmoid_fast(float v) {
    return __fdividef(1.0f, 1.0f + __expf(-v));
}
__device__ __forceinline__ float tanh_fast(float v) {
    float z = __expf(-2.0f * v);
    return __fdividef(1.0f - z, 1.0f + z);
}

// ---------------------------------------------------------------------------
// Kernel 1: per-site UGRNN recurrence. ONE thread = ONE site, f32x2 math.
// No shuffles; all weight LDS are 32-lane broadcasts; accumulators packed.
// ---------------------------------------------------------------------------
__global__ __launch_bounds__(128, 3)
void ugrnn_kernel(const float* __restrict__ inputs,
                  const float* __restrict__ Wn,
                  const float* __restrict__ Wg,
                  const float* __restrict__ Ug,
                  const float* __restrict__ bg,
                  const float* __restrict__ Wc,
                  const float* __restrict__ Uc,
                  const float* __restrict__ bc,
                  const float* __restrict__ We,
                  const float* __restrict__ be)
{
    __shared__ __align__(16) float sWn[K_DIM * U_DIM];   // 512
    __shared__ __align__(16) float sWg[U_DIM * U_DIM];
    __shared__ __align__(16) float sUg[U_DIM * U_DIM];
    __shared__ __align__(16) float sWc[U_DIM * U_DIM];
    __shared__ __align__(16) float sUc[U_DIM * U_DIM];
    __shared__ __align__(16) float sWe[U_DIM * U_DIM];
    __shared__ __align__(16) float sb[3 * U_DIM];

    const int tid = threadIdx.x;
    for (int i = tid; i < K_DIM * U_DIM; i += 128) sWn[i] = Wn[i];
    for (int i = tid; i < U_DIM * U_DIM; i += 128) {
        sWg[i] = Wg[i]; sUg[i] = Ug[i];
        sWc[i] = Wc[i]; sUc[i] = Uc[i];
        sWe[i] = We[i];
    }
    if (tid < U_DIM) {
        sb[tid]              = bg[tid];
        sb[U_DIM + tid]      = bc[tid];
        sb[2 * U_DIM + tid]  = be[tid];
    }
    __syncthreads();

    const int site = blockIdx.x * 128 + tid;   // 0 .. BN-1
    const float* __restrict__ row = inputs + (long long)site * ROWLEN;

    const float h0 = __ldg(&row[0]);
    const float e0 = __ldg(&row[K_DIM + 1]);

    // m (packed accumulate over k): m2[q] holds units {2q, 2q+1}
    u64 m2[8];
#pragma unroll
    for (int q = 0; q < 8; q++) m2[q] = 0ull;   // two packed 0.0f
#pragma unroll 4
    for (int k = 0; k < K_DIM; k++) {
        float nk = __ldg(&row[1 + k]);
        u64 nk2 = pk2(nk, nk);
        const ulonglong2* wr = (const ulonglong2*)&sWn[k * U_DIM];
#pragma unroll
        for (int t = 0; t < 4; t++) {           // 4 x ulonglong2 = 16 floats
            ulonglong2 w = wr[t];
            m2[t * 2 + 0] = ffma2(nk2, w.x, m2[t * 2 + 0]);
            m2[t * 2 + 1] = ffma2(nk2, w.y, m2[t * 2 + 1]);
        }
    }
    float ms[U_DIM];
#pragma unroll
    for (int q = 0; q < 8; q++) upk2(ms[2 * q], ms[2 * q + 1], m2[q]);

    float hs[U_DIM], es[U_DIM];
#pragma unroll
    for (int u = 0; u < U_DIM; u++) { hs[u] = h0; es[u] = e0; }

#pragma unroll 1
    for (int step = 0; step < NUM_STEPS; step++) {
        float xs[U_DIM];
#pragma unroll
        for (int u = 0; u < U_DIM; u++) xs[u] = ms[u] + es[u];

        // fused g + c accumulation (8 packed accs each, ALL 16 units)
        u64 ag[8], ac[8];
        {
            const ulonglong2* bgp = (const ulonglong2*)&sb[0];
            const ulonglong2* bcp = (const ulonglong2*)&sb[U_DIM];
#pragma unroll
            for (int t = 0; t < 4; t++) {
                ulonglong2 bgv = bgp[t];
                ulonglong2 bcv = bcp[t];
                ag[t * 2 + 0] = bgv.x; ag[t * 2 + 1] = bgv.y;
                ac[t * 2 + 0] = bcv.x; ac[t * 2 + 1] = bcv.y;
            }
        }

#pragma unroll
        for (int j = 0; j < U_DIM; j++) {
            const u64 xj2 = pk2(xs[j], xs[j]);
            const u64 hj2 = pk2(hs[j], hs[j]);
            const ulonglong2* wg = (const ulonglong2*)&sWg[j * U_DIM];
            const ulonglong2* ug = (const ulonglong2*)&sUg[j * U_DIM];
            const ulonglong2* wc = (const ulonglong2*)&sWc[j * U_DIM];
            const ulonglong2* uc = (const ulonglong2*)&sUc[j * U_DIM];
#pragma unroll
            for (int t = 0; t < 4; t++) {       // 4 x ulonglong2 = 16 floats
                ulonglong2 wgv = wg[t], ugv = ug[t];
                ag[t * 2 + 0] = ffma2(xj2, wgv.x, ffma2(hj2, ugv.x, ag[t * 2 + 0]));
                ag[t * 2 + 1] = ffma2(xj2, wgv.y, ffma2(hj2, ugv.y, ag[t * 2 + 1]));
                ulonglong2 wcv = wc[t], ucv = uc[t];
                ac[t * 2 + 0] = ffma2(xj2, wcv.x, ffma2(hj2, ucv.x, ac[t * 2 + 0]));
                ac[t * 2 + 1] = ffma2(xj2, wcv.y, ffma2(hj2, ucv.y, ac[t * 2 + 1]));
            }
        }

        // activations + h update (scalar)
#pragma unroll
        for (int q = 0; q < 8; q++) {
            float a0, a1, c0, c1;
            upk2(a0, a1, ag[q]);
            upk2(c0, c1, ac[q]);
            float g0 = sigmoid_fast(a0);
            float g1 = sigmoid_fast(a1);
            float cc0 = tanh_fast(c0);
            float cc1 = tanh_fast(c1);
            hs[2 * q + 0] = fmaf(g0, hs[2 * q + 0] - cc0, cc0);
            hs[2 * q + 1] = fmaf(g1, hs[2 * q + 1] - cc1, cc1);
        }

        // e = tanh(x@We + be)  (skip on last step: result unused)
        if (step < NUM_STEPS - 1) {
            u64 ae[8];
            {
                const ulonglong2* bep = (const ulonglong2*)&sb[2 * U_DIM];
#pragma unroll
                for (int t = 0; t < 4; t++) {
                    ulonglong2 bev = bep[t];
                    ae[t * 2 + 0] = bev.x; ae[t * 2 + 1] = bev.y;
                }
            }
#pragma unroll
            for (int j = 0; j < U_DIM; j++) {
                const u64 xj2 = pk2(xs[j], xs[j]);
                const ulonglong2* we = (const ulonglong2*)&sWe[j * U_DIM];
#pragma unroll
                for (int t = 0; t < 4; t++) {   // 4 x ulonglong2 = 16 floats
                    ulonglong2 wev = we[t];
                    ae[t * 2 + 0] = ffma2(xj2, wev.x, ae[t * 2 + 0]);
                    ae[t * 2 + 1] = ffma2(xj2, wev.y, ae[t * 2 + 1]);
                }
            }
#pragma unroll
            for (int q = 0; q < 8; q++) {
                float a0, a1;
                upk2(a0, a1, ae[q]);
                es[2 * q + 0] = tanh_fast(a0);
                es[2 * q + 1] = tanh_fast(a1);
            }
        }
    }

    float* __restrict__ dst = g_h + (long long)site * U_DIM;
#pragma unroll
    for (int q = 0; q < 4; q++) {
        float4 v = make_float4(hs[q * 4 + 0], hs[q * 4 + 1], hs[q * 4 + 2], hs[q * 4 + 3]);
        *(float4*)&dst[q * 4] = v;
    }
}

// ---------------------------------------------------------------------------
// Kernel 2: split-K GEMM: part[split] = A(64 x KCHUNK) * W1(KCHUNK x 256)
// f32x2 inner product (bit-identical order to scalar version).
// ---------------------------------------------------------------------------
__global__ __launch_bounds__(256, 2)
void gemm1_kernel(const float* __restrict__ W1)
{
    __shared__ __align__(16) float As[16][B_DIM];     // [k][row]
    __shared__ __align__(16) float Bs[16][H1];        // [k][col]

    const int split = blockIdx.x;
    const int k0 = split * KCHUNK;
    const int tid = threadIdx.x;
    const int tm = tid >> 5;            // 0..7  -> rows tm*8 .. tm*8+7
    const int tn = tid & 31;            // 0..31 -> cols tn*8 .. tn*8+7

    u64 acc2[8][4];
#pragma unroll
    for (int i = 0; i < 8; i++)
#pragma unroll
        for (int j = 0; j < 4; j++) acc2[i][j] = 0ull;

    const int ar = tid >> 2;             // row 0..63
    const int akq = (tid & 3) * 4;       // k offset 0,4,8,12

    for (int kk = 0; kk < KCHUNK; kk += 16) {
        float4 av = *(const float4*)&g_h[(long long)ar * NU + k0 + kk + akq];
        As[akq + 0][ar] = av.x;
        As[akq + 1][ar] = av.y;
        As[akq + 2][ar] = av.z;
        As[akq + 3][ar] = av.w;
#pragma unroll
        for (int i = 0; i < 4; i++) {
            int idx = tid + i * 256;          // float4 index
            int kr = idx >> 6;                // 0..15
            int cq = (idx & 63) * 4;          // col 0..252
            float4 bv = *(const float4*)&W1[(long long)(k0 + kk + kr) * H1 + cq];
            *(float4*)&Bs[kr][cq] = bv;
        }
        __syncthreads();

#pragma unroll
        for (int k = 0; k < 16; k++) {
            float a[8];
            float4 a0 = *(const float4*)&As[k][tm * 8];
            float4 a1 = *(const float4*)&As[k][tm * 8 + 4];
            a[0] = a0.x; a[1] = a0.y; a[2] = a0.z; a[3] = a0.w;
            a[4] = a1.x; a[5] = a1.y; a[6] = a1.z; a[7] = a1.w;
            u64 b2[4];
            {
                const ulonglong2* bp = (const ulonglong2*)&Bs[k][tn * 8];
                ulonglong2 q0 = bp[0];
                ulonglong2 q1 = bp[1];
                b2[0] = q0.x; b2[1] = q0.y; b2[2] = q1.x; b2[3] = q1.y;
            }
#pragma unroll
            for (int i = 0; i < 8; i++) {
                u64 a2 = pk2(a[i], a[i]);
#pragma unroll
                for (int j = 0; j < 4; j++)
                    acc2[i][j] = ffma2(a2, b2[j], acc2[i][j]);
            }
        }
        __syncthreads();
    }

    float* __restrict__ out = g_part + (long long)split * (B_DIM * H1);
#pragma unroll
    for (int i = 0; i < 8; i++) {
        int r = tm * 8 + i;
#pragma unroll
        for (int j = 0; j < 4; j++) {
            float lo, hi;
            upk2(lo, hi, acc2[i][j]);
            out[r * H1 + tn * 8 + 2 * j + 0] = lo;
            out[r * H1 + tn * 8 + 2 * j + 1] = hi;
        }
    }
}

// ---------------------------------------------------------------------------
// Kernel 3: reduce split-K partials + bias + relu, then layers 2/3 + softmax.
// ---------------------------------------------------------------------------
__global__ __launch_bounds__(256, 1)
void mlp_kernel(const float* __restrict__ b1,
                const float* __restrict__ W2,
                const float* __restrict__ b2,
                const float* __restrict__ W3,
                const float* __restrict__ b3,
                float* __restrict__ out)
{
    __shared__ float sv[H1];
    __shared__ float s2[H2];
    __shared__ float sl[NCLS];

    const int b = blockIdx.x;
    const int o = threadIdx.x;

    const float* __restrict__ p = g_part + (long long)b * H1 + o;
    float s0 = 0.f, s1 = 0.f, s2a = 0.f, s3 = 0.f;
#pragma unroll 4
    for (int s = 0; s < NSPLIT; s += 4) {
        s0  += p[(long long)(s + 0) * (B_DIM * H1)];
        s1  += p[(long long)(s + 1) * (B_DIM * H1)];
        s2a += p[(long long)(s + 2) * (B_DIM * H1)];
        s3  += p[(long long)(s + 3) * (B_DIM * H1)];
    }
    float v = b1[o] + ((s0 + s1) + (s2a + s3));
    sv[o] = fmaxf(v, 0.0f);
    __syncthreads();

    if (o < H2) {
        float a = b2[o];
#pragma unroll 8
        for (int i = 0; i < H1; i++)
            a = fmaf(sv[i], W2[i * H2 + o], a);
        s2[o] = fmaxf(a, 0.0f);
    }
    __syncthreads();

    if (o < NCLS) {
        float a = b3[o];
#pragma unroll
        for (int j = 0; j < H2; j++)
            a = fmaf(s2[j], W3[j * NCLS + o], a);
        sl[o] = a;
    }
    __syncthreads();

    if (o == 0) {
        float mx = fmaxf(sl[0], sl[1]);
        float e0 = __expf(sl[0] - mx);
        float e1 = __expf(sl[1] - mx);
        float inv = __fdividef(1.0f, e0 + e1);
        out[b * NCLS + 0] = e0 * inv;
        out[b * NCLS + 1] = e1 * inv;
    }
}

// ---------------------------------------------------------------------------
extern "C" void kernel_launch(void* const* d_in, const int* in_sizes, int n_in,
                              void* d_out, int out_size)
{
    const float* inputs = (const float*)d_in[0];
    const float* Wn = (const float*)d_in[1];
    const float* Wg = (const float*)d_in[2];
    const float* Ug = (const float*)d_in[3];
    const float* bg = (const float*)d_in[4];
    const float* Wc = (const float*)d_in[5];
    const float* Uc = (const float*)d_in[6];
    const float* bc = (const float*)d_in[7];
    const float* We = (const float*)d_in[8];
    const float* be = (const float*)d_in[9];
    const float* W1 = (const float*)d_in[10];
    const float* b1 = (const float*)d_in[11];
    const float* W2 = (const float*)d_in[12];
    const float* b2 = (const float*)d_in[13];
    const float* W3 = (const float*)d_in[14];
    const float* b3 = (const float*)d_in[15];
    float* out = (float*)d_out;

    ugrnn_kernel<<<BN / 128, 128>>>(inputs, Wn, Wg, Ug, bg, Wc, Uc, bc, We, be);
    gemm1_kernel<<<NSPLIT, 256>>>(W1);
    mlp_kernel<<<B_DIM, 256>>>(b1, W2, b2, W3, b3, out);
}

// round 11
// speedup vs baseline: 8.3712x; 8.3712x over previous
#include <cuda_runtime.h>
#include <math.h>

#define B_DIM 64
#define N_DIM 4096
#define K_DIM 32
#define U_DIM 16
#define NUM_STEPS 8
#define BN (B_DIM * N_DIM)            // 262144 sites
#define NU (N_DIM * U_DIM)            // 65536 (GEMM K)
#define H1 256
#define H2 32
#define NCLS 2
#define ROWLEN (K_DIM + 2)            // 34

#define NSPLIT 256
#define KCHUNK (NU / NSPLIT)          // 256

// scratch (device globals: allocation-free)
__device__ float g_h[BN * U_DIM];               // 16 MB: h outputs (B, N*U) row-major
__device__ float g_part[NSPLIT * B_DIM * H1];   // 16 MB: split-K partials

// weights in constant memory: warp-uniform access -> LDCU uniform-const port,
// zero L1TEX/LSU traffic, no GPR temps for weights.
__constant__ float cWn[K_DIM * U_DIM];   // 512
__constant__ float cWg[U_DIM * U_DIM];
__constant__ float cUg[U_DIM * U_DIM];
__constant__ float cWc[U_DIM * U_DIM];
__constant__ float cUc[U_DIM * U_DIM];
__constant__ float cWe[U_DIM * U_DIM];
__constant__ float cb[3 * U_DIM];        // bg | bc | be

__device__ __forceinline__ float sigmoid_fast(float v) {
    return __fdividef(1.0f, 1.0f + __expf(-v));
}
__device__ __forceinline__ float tanh_fast(float v) {
    float z = __expf(-2.0f * v);
    return __fdividef(1.0f - z, 1.0f + z);
}

// ---------------------------------------------------------------------------
// Kernel 1: per-site UGRNN recurrence. ONE thread = ONE site; weights from
// constant memory with immediate (warp-uniform) indices. Sequential 3-pass
// gate structure keeps peak live set ~100 regs.
// ---------------------------------------------------------------------------
__global__ __launch_bounds__(128, 4)
void ugrnn_kernel(const float* __restrict__ inputs)
{
    const int site = blockIdx.x * 128 + threadIdx.x;   // 0 .. BN-1
    const float* __restrict__ row = inputs + (long long)site * ROWLEN;

    const float h0 = __ldg(&row[0]);
    const float e0 = __ldg(&row[K_DIM + 1]);

    // m[u] = sum_k neigh[k] * Wn[k][u]
    float ms[U_DIM];
#pragma unroll
    for (int u = 0; u < U_DIM; u++) ms[u] = 0.0f;
#pragma unroll 4
    for (int k = 0; k < K_DIM; k++) {
        float nk = __ldg(&row[1 + k]);
#pragma unroll
        for (int u = 0; u < U_DIM; u++)
            ms[u] = fmaf(nk, cWn[k * U_DIM + u], ms[u]);
    }

    float hs[U_DIM], es[U_DIM];
#pragma unroll
    for (int u = 0; u < U_DIM; u++) { hs[u] = h0; es[u] = e0; }

#pragma unroll 1
    for (int step = 0; step < NUM_STEPS; step++) {
        // x = m + e, stored in place into es (es dead until pass 3 rewrites it)
#pragma unroll
        for (int u = 0; u < U_DIM; u++) es[u] = ms[u] + es[u];

        // ---- pass 1: g = sigmoid(x@Wg + h@Ug + bg) ----
        float g[U_DIM];
        {
            float acc[U_DIM];
#pragma unroll
            for (int u = 0; u < U_DIM; u++) acc[u] = cb[u];
#pragma unroll
            for (int j = 0; j < U_DIM; j++) {
                const float xj = es[j];
                const float hj = hs[j];
#pragma unroll
                for (int u = 0; u < U_DIM; u++)
                    acc[u] = fmaf(xj, cWg[j * U_DIM + u],
                             fmaf(hj, cUg[j * U_DIM + u], acc[u]));
            }
#pragma unroll
            for (int u = 0; u < U_DIM; u++) g[u] = sigmoid_fast(acc[u]);
        }

        // ---- pass 2: c = tanh(x@Wc + h@Uc + bc); h = g*h + (1-g)*c ----
        {
            float acc[U_DIM];
#pragma unroll
            for (int u = 0; u < U_DIM; u++) acc[u] = cb[U_DIM + u];
#pragma unroll
            for (int j = 0; j < U_DIM; j++) {
                const float xj = es[j];
                const float hj = hs[j];
#pragma unroll
                for (int u = 0; u < U_DIM; u++)
                    acc[u] = fmaf(xj, cWc[j * U_DIM + u],
                             fmaf(hj, cUc[j * U_DIM + u], acc[u]));
            }
#pragma unroll
            for (int u = 0; u < U_DIM; u++) {
                float c = tanh_fast(acc[u]);
                hs[u] = fmaf(g[u], hs[u] - c, c);   // g*h + (1-g)*c
            }
        }

        // ---- pass 3: e = tanh(x@We + be)  (skip on last step: unused) ----
        if (step < NUM_STEPS - 1) {
            float acc[U_DIM];
#pragma unroll
            for (int u = 0; u < U_DIM; u++) acc[u] = cb[2 * U_DIM + u];
#pragma unroll
            for (int j = 0; j < U_DIM; j++) {
                const float xj = es[j];
#pragma unroll
                for (int u = 0; u < U_DIM; u++)
                    acc[u] = fmaf(xj, cWe[j * U_DIM + u], acc[u]);
            }
#pragma unroll
            for (int u = 0; u < U_DIM; u++) es[u] = tanh_fast(acc[u]);
        }
    }

    float* __restrict__ dst = g_h + (long long)site * U_DIM;
#pragma unroll
    for (int q = 0; q < 4; q++) {
        float4 v = make_float4(hs[q * 4 + 0], hs[q * 4 + 1], hs[q * 4 + 2], hs[q * 4 + 3]);
        *(float4*)&dst[q * 4] = v;
    }
}

// ---------------------------------------------------------------------------
// Kernel 2: split-K GEMM: part[split] = A(64 x KCHUNK) * W1(KCHUNK x 256)
// Classic 8x8 register tiling (R7 version, known good).
// ---------------------------------------------------------------------------
__global__ __launch_bounds__(256, 2)
void gemm1_kernel(const float* __restrict__ W1)
{
    __shared__ __align__(16) float As[16][B_DIM];     // [k][row]
    __shared__ __align__(16) float Bs[16][H1];        // [k][col]

    const int split = blockIdx.x;
    const int k0 = split * KCHUNK;
    const int tid = threadIdx.x;
    const int tm = tid >> 5;            // 0..7  -> rows tm*8 .. tm*8+7
    const int tn = tid & 31;            // 0..31 -> cols tn*8 .. tn*8+7

    float acc[8][8];
#pragma unroll
    for (int i = 0; i < 8; i++)
#pragma unroll
        for (int j = 0; j < 8; j++) acc[i][j] = 0.0f;

    const int ar = tid >> 2;             // row 0..63
    const int akq = (tid & 3) * 4;       // k offset 0,4,8,12

    for (int kk = 0; kk < KCHUNK; kk += 16) {
        float4 av = *(const float4*)&g_h[(long long)ar * NU + k0 + kk + akq];
        As[akq + 0][ar] = av.x;
        As[akq + 1][ar] = av.y;
        As[akq + 2][ar] = av.z;
        As[akq + 3][ar] = av.w;
#pragma unroll
        for (int i = 0; i < 4; i++) {
            int idx = tid + i * 256;          // float4 index
            int kr = idx >> 6;                // 0..15
            int cq = (idx & 63) * 4;          // col 0..252
            float4 bv = *(const float4*)&W1[(long long)(k0 + kk + kr) * H1 + cq];
            *(float4*)&Bs[kr][cq] = bv;
        }
        __syncthreads();

#pragma unroll
        for (int k = 0; k < 16; k++) {
            float a[8], b[8];
            float4 a0 = *(const float4*)&As[k][tm * 8];
            float4 a1 = *(const float4*)&As[k][tm * 8 + 4];
            a[0] = a0.x; a[1] = a0.y; a[2] = a0.z; a[3] = a0.w;
            a[4] = a1.x; a[5] = a1.y; a[6] = a1.z; a[7] = a1.w;
            float4 b0 = *(const float4*)&Bs[k][tn * 8];
            float4 b1 = *(const float4*)&Bs[k][tn * 8 + 4];
            b[0] = b0.x; b[1] = b0.y; b[2] = b0.z; b[3] = b0.w;
            b[4] = b1.x; b[5] = b1.y; b[6] = b1.z; b[7] = b1.w;
#pragma unroll
            for (int i = 0; i < 8; i++)
#pragma unroll
                for (int j = 0; j < 8; j++)
                    acc[i][j] = fmaf(a[i], b[j], acc[i][j]);
        }
        __syncthreads();
    }

    float* __restrict__ out = g_part + (long long)split * (B_DIM * H1);
#pragma unroll
    for (int i = 0; i < 8; i++) {
        int r = tm * 8 + i;
#pragma unroll
        for (int j = 0; j < 8; j++)
            out[r * H1 + tn * 8 + j] = acc[i][j];
    }
}

// ---------------------------------------------------------------------------
// Kernel 3: reduce split-K partials + bias + relu, then layers 2/3 + softmax.
// ---------------------------------------------------------------------------
__global__ __launch_bounds__(256, 1)
void mlp_kernel(const float* __restrict__ b1,
                const float* __restrict__ W2,
                const float* __restrict__ b2,
                const float* __restrict__ W3,
                const float* __restrict__ b3,
                float* __restrict__ out)
{
    __shared__ float sv[H1];
    __shared__ float s2[H2];
    __shared__ float sl[NCLS];

    const int b = blockIdx.x;
    const int o = threadIdx.x;

    const float* __restrict__ p = g_part + (long long)b * H1 + o;
    float s0 = 0.f, s1 = 0.f, s2a = 0.f, s3 = 0.f;
#pragma unroll 4
    for (int s = 0; s < NSPLIT; s += 4) {
        s0  += p[(long long)(s + 0) * (B_DIM * H1)];
        s1  += p[(long long)(s + 1) * (B_DIM * H1)];
        s2a += p[(long long)(s + 2) * (B_DIM * H1)];
        s3  += p[(long long)(s + 3) * (B_DIM * H1)];
    }
    float v = b1[o] + ((s0 + s1) + (s2a + s3));
    sv[o] = fmaxf(v, 0.0f);
    __syncthreads();

    if (o < H2) {
        float a = b2[o];
#pragma unroll 8
        for (int i = 0; i < H1; i++)
            a = fmaf(sv[i], W2[i * H2 + o], a);
        s2[o] = fmaxf(a, 0.0f);
    }
    __syncthreads();

    if (o < NCLS) {
        float a = b3[o];
#pragma unroll
        for (int j = 0; j < H2; j++)
            a = fmaf(s2[j], W3[j * NCLS + o], a);
        sl[o] = a;
    }
    __syncthreads();

    if (o == 0) {
        float mx = fmaxf(sl[0], sl[1]);
        float e0 = __expf(sl[0] - mx);
        float e1 = __expf(sl[1] - mx);
        float inv = __fdividef(1.0f, e0 + e1);
        out[b * NCLS + 0] = e0 * inv;
        out[b * NCLS + 1] = e1 * inv;
    }
}

// ---------------------------------------------------------------------------
extern "C" void kernel_launch(void* const* d_in, const int* in_sizes, int n_in,
                              void* d_out, int out_size)
{
    const float* inputs = (const float*)d_in[0];
    const float* Wn = (const float*)d_in[1];
    const float* Wg = (const float*)d_in[2];
    const float* Ug = (const float*)d_in[3];
    const float* bg = (const float*)d_in[4];
    const float* Wc = (const float*)d_in[5];
    const float* Uc = (const float*)d_in[6];
    const float* bc = (const float*)d_in[7];
    const float* We = (const float*)d_in[8];
    const float* be = (const float*)d_in[9];
    const float* W1 = (const float*)d_in[10];
    const float* b1 = (const float*)d_in[11];
    const float* W2 = (const float*)d_in[12];
    const float* b2 = (const float*)d_in[13];
    const float* W3 = (const float*)d_in[14];
    const float* b3 = (const float*)d_in[15];
    float* out = (float*)d_out;

    // async D2D copies into constant bank (graph-capturable)
    cudaMemcpyToSymbolAsync(cWn, Wn, K_DIM * U_DIM * sizeof(float), 0, cudaMemcpyDeviceToDevice, 0);
    cudaMemcpyToSymbolAsync(cWg, Wg, U_DIM * U_DIM * sizeof(float), 0, cudaMemcpyDeviceToDevice, 0);
    cudaMemcpyToSymbolAsync(cUg, Ug, U_DIM * U_DIM * sizeof(float), 0, cudaMemcpyDeviceToDevice, 0);
    cudaMemcpyToSymbolAsync(cWc, Wc, U_DIM * U_DIM * sizeof(float), 0, cudaMemcpyDeviceToDevice, 0);
    cudaMemcpyToSymbolAsync(cUc, Uc, U_DIM * U_DIM * sizeof(float), 0, cudaMemcpyDeviceToDevice, 0);
    cudaMemcpyToSymbolAsync(cWe, We, U_DIM * U_DIM * sizeof(float), 0, cudaMemcpyDeviceToDevice, 0);
    cudaMemcpyToSymbolAsync(cb, bg, U_DIM * sizeof(float), 0 * U_DIM * sizeof(float), cudaMemcpyDeviceToDevice, 0);
    cudaMemcpyToSymbolAsync(cb, bc, U_DIM * sizeof(float), 1 * U_DIM * sizeof(float), cudaMemcpyDeviceToDevice, 0);
    cudaMemcpyToSymbolAsync(cb, be, U_DIM * sizeof(float), 2 * U_DIM * sizeof(float), cudaMemcpyDeviceToDevice, 0);

    ugrnn_kernel<<<BN / 128, 128>>>(inputs);
    gemm1_kernel<<<NSPLIT, 256>>>(W1);
    mlp_kernel<<<B_DIM, 256>>>(b1, W2, b2, W3, b3, out);
}

// round 13
// speedup vs baseline: 8.4433x; 1.0086x over previous
#include <cuda_runtime.h>
#include <math.h>

#define B_DIM 64
#define N_DIM 4096
#define K_DIM 32
#define U_DIM 16
#define NUM_STEPS 8
#define BN (B_DIM * N_DIM)            // 262144 sites
#define NU (N_DIM * U_DIM)            // 65536 (GEMM K)
#define H1 256
#define H2 32
#define NCLS 2
#define ROWLEN (K_DIM + 2)            // 34

#define NSPLIT 256
#define KCHUNK (NU / NSPLIT)          // 256
#define NGRP 16                       // phase-A reduction groups
#define SPG (NSPLIT / NGRP)           // 16 splits per group

// scratch (device globals: allocation-free)
__device__ float g_h[BN * U_DIM];               // 16 MB: h outputs
__device__ float g_part[NSPLIT * B_DIM * H1];   // 16 MB: split-K partials
__device__ float g_part2[NGRP * B_DIM * H1];    // 1 MB: phase-A partials

// weights in constant memory: warp-uniform -> LDCU uniform port
__constant__ __align__(16) float cWn[K_DIM * U_DIM];
__constant__ __align__(16) float cWg[U_DIM * U_DIM];
__constant__ __align__(16) float cUg[U_DIM * U_DIM];
__constant__ __align__(16) float cWc[U_DIM * U_DIM];
__constant__ __align__(16) float cUc[U_DIM * U_DIM];
__constant__ __align__(16) float cWe[U_DIM * U_DIM];
__constant__ __align__(16) float cb[3 * U_DIM];   // bg | bc | be

typedef unsigned long long u64;

// ---- f32x2 packed helpers (componentwise fp32: bit-identical to scalar) ----
__device__ __forceinline__ u64 pk2(float lo, float hi) {
    u64 r;
    asm("mov.b64 %0, {%1, %2};" : "=l"(r) : "f"(lo), "f"(hi));
    return r;
}
__device__ __forceinline__ void upk2(float& lo, float& hi, u64 v) {
    asm("mov.b64 {%0, %1}, %2;" : "=f"(lo), "=f"(hi) : "l"(v));
}
__device__ __forceinline__ u64 ffma2(u64 a, u64 b, u64 c) {
    u64 d;
    asm("fma.rn.f32x2 %0, %1, %2, %3;" : "=l"(d) : "l"(a), "l"(b), "l"(c));
    return d;
}
__device__ __forceinline__ u64 cld2(const float* p) {   // 8B const load
    return *(const u64*)p;
}

__device__ __forceinline__ float sigmoid_fast(float v) {
    return __fdividef(1.0f, 1.0f + __expf(-v));
}
__device__ __forceinline__ float tanh_fast(float v) {
    float z = __expf(-2.0f * v);
    return __fdividef(1.0f - z, 1.0f + z);
}

// ---------------------------------------------------------------------------
// Kernel 1: UGRNN. 1 thread = 1 site; weights uniform from constant;
// f32x2-packed accumulators, one 8-wide packed acc live at a time (3 passes).
// ---------------------------------------------------------------------------
__global__ __launch_bounds__(128, 4)
void ugrnn_kernel(const float* __restrict__ inputs)
{
    const int site = blockIdx.x * 128 + threadIdx.x;   // 0 .. BN-1
    const float* __restrict__ row = inputs + (long long)site * ROWLEN;

    const float h0 = __ldg(&row[0]);
    const float e0 = __ldg(&row[K_DIM + 1]);

    // m[u] = sum_k neigh[k] * Wn[k][u]  (packed: acc q holds units {2q,2q+1})
    float ms[U_DIM];
    {
        u64 m2[8];
#pragma unroll
        for (int q = 0; q < 8; q++) m2[q] = 0ull;
#pragma unroll 4
        for (int k = 0; k < K_DIM; k++) {
            float nk = __ldg(&row[1 + k]);
            u64 nk2 = pk2(nk, nk);
#pragma unroll
            for (int q = 0; q < 8; q++)
                m2[q] = ffma2(nk2, cld2(&cWn[k * U_DIM + 2 * q]), m2[q]);
        }
#pragma unroll
        for (int q = 0; q < 8; q++) upk2(ms[2 * q], ms[2 * q + 1], m2[q]);
    }

    float hs[U_DIM], es[U_DIM];
#pragma unroll
    for (int u = 0; u < U_DIM; u++) { hs[u] = h0; es[u] = e0; }

#pragma unroll 1
    for (int step = 0; step < NUM_STEPS; step++) {
        // x = m + e, in place into es (es dead until pass 3 rewrites it)
#pragma unroll
        for (int u = 0; u < U_DIM; u++) es[u] = ms[u] + es[u];

        // ---- pass 1: g = sigmoid(x@Wg + h@Ug + bg) ----
        float g[U_DIM];
        {
            u64 acc[8];
#pragma unroll
            for (int q = 0; q < 8; q++) acc[q] = cld2(&cb[2 * q]);
#pragma unroll
            for (int j = 0; j < U_DIM; j++) {
                const u64 xj2 = pk2(es[j], es[j]);
                const u64 hj2 = pk2(hs[j], hs[j]);
#pragma unroll
                for (int q = 0; q < 8; q++)
                    acc[q] = ffma2(xj2, cld2(&cWg[j * U_DIM + 2 * q]),
                             ffma2(hj2, cld2(&cUg[j * U_DIM + 2 * q]), acc[q]));
            }
#pragma unroll
            for (int q = 0; q < 8; q++) {
                float a0, a1;
                upk2(a0, a1, acc[q]);
                g[2 * q + 0] = sigmoid_fast(a0);
                g[2 * q + 1] = sigmoid_fast(a1);
            }
        }

        // ---- pass 2: c = tanh(x@Wc + h@Uc + bc); h = g*h + (1-g)*c ----
        {
            u64 acc[8];
#pragma unroll
            for (int q = 0; q < 8; q++) acc[q] = cld2(&cb[U_DIM + 2 * q]);
#pragma unroll
            for (int j = 0; j < U_DIM; j++) {
                const u64 xj2 = pk2(es[j], es[j]);
                const u64 hj2 = pk2(hs[j], hs[j]);
#pragma unroll
                for (int q = 0; q < 8; q++)
                    acc[q] = ffma2(xj2, cld2(&cWc[j * U_DIM + 2 * q]),
                             ffma2(hj2, cld2(&cUc[j * U_DIM + 2 * q]), acc[q]));
            }
#pragma unroll
            for (int q = 0; q < 8; q++) {
                float a0, a1;
                upk2(a0, a1, acc[q]);
                float c0 = tanh_fast(a0);
                float c1 = tanh_fast(a1);
                hs[2 * q + 0] = fmaf(g[2 * q + 0], hs[2 * q + 0] - c0, c0);
                hs[2 * q + 1] = fmaf(g[2 * q + 1], hs[2 * q + 1] - c1, c1);
            }
        }

        // ---- pass 3: e = tanh(x@We + be)  (skip on last step: unused) ----
        if (step < NUM_STEPS - 1) {
            u64 acc[8];
#pragma unroll
            for (int q = 0; q < 8; q++) acc[q] = cld2(&cb[2 * U_DIM + 2 * q]);
#pragma unroll
            for (int j = 0; j < U_DIM; j++) {
                const u64 xj2 = pk2(es[j], es[j]);
#pragma unroll
                for (int q = 0; q < 8; q++)
                    acc[q] = ffma2(xj2, cld2(&cWe[j * U_DIM + 2 * q]), acc[q]);
            }
#pragma unroll
            for (int q = 0; q < 8; q++) {
                float a0, a1;
                upk2(a0, a1, acc[q]);
                es[2 * q + 0] = tanh_fast(a0);
                es[2 * q + 1] = tanh_fast(a1);
            }
        }
    }

    float* __restrict__ dst = g_h + (long long)site * U_DIM;
#pragma unroll
    for (int q = 0; q < 4; q++) {
        float4 v = make_float4(hs[q * 4 + 0], hs[q * 4 + 1], hs[q * 4 + 2], hs[q * 4 + 3]);
        *(float4*)&dst[q * 4] = v;
    }
}

// ---------------------------------------------------------------------------
// Kernel 2: split-K GEMM (f32x2 inner product — validated in R9).
// ---------------------------------------------------------------------------
__global__ __launch_bounds__(256, 2)
void gemm1_kernel(const float* __restrict__ W1)
{
    __shared__ __align__(16) float As[16][B_DIM];     // [k][row]
    __shared__ __align__(16) float Bs[16][H1];        // [k][col]

    const int split = blockIdx.x;
    const int k0 = split * KCHUNK;
    const int tid = threadIdx.x;
    const int tm = tid >> 5;            // 0..7
    const int tn = tid & 31;            // 0..31

    u64 acc2[8][4];
#pragma unroll
    for (int i = 0; i < 8; i++)
#pragma unroll
        for (int j = 0; j < 4; j++) acc2[i][j] = 0ull;

    const int ar = tid >> 2;             // row 0..63
    const int akq = (tid & 3) * 4;       // k offset 0,4,8,12

    for (int kk = 0; kk < KCHUNK; kk += 16) {
        float4 av = *(const float4*)&g_h[(long long)ar * NU + k0 + kk + akq];
        As[akq + 0][ar] = av.x;
        As[akq + 1][ar] = av.y;
        As[akq + 2][ar] = av.z;
        As[akq + 3][ar] = av.w;
#pragma unroll
        for (int i = 0; i < 4; i++) {
            int idx = tid + i * 256;
            int kr = idx >> 6;
            int cq = (idx & 63) * 4;
            float4 bv = *(const float4*)&W1[(long long)(k0 + kk + kr) * H1 + cq];
            *(float4*)&Bs[kr][cq] = bv;
        }
        __syncthreads();

#pragma unroll
        for (int k = 0; k < 16; k++) {
            float a[8];
            float4 a0 = *(const float4*)&As[k][tm * 8];
            float4 a1 = *(const float4*)&As[k][tm * 8 + 4];
            a[0] = a0.x; a[1] = a0.y; a[2] = a0.z; a[3] = a0.w;
            a[4] = a1.x; a[5] = a1.y; a[6] = a1.z; a[7] = a1.w;
            u64 b2[4];
            {
                const ulonglong2* bp = (const ulonglong2*)&Bs[k][tn * 8];
                ulonglong2 q0 = bp[0];
                ulonglong2 q1 = bp[1];
                b2[0] = q0.x; b2[1] = q0.y; b2[2] = q1.x; b2[3] = q1.y;
            }
#pragma unroll
            for (int i = 0; i < 8; i++) {
                u64 a2 = pk2(a[i], a[i]);
#pragma unroll
                for (int j = 0; j < 4; j++)
                    acc2[i][j] = ffma2(a2, b2[j], acc2[i][j]);
            }
        }
        __syncthreads();
    }

    float* __restrict__ out = g_part + (long long)split * (B_DIM * H1);
#pragma unroll
    for (int i = 0; i < 8; i++) {
        int r = tm * 8 + i;
#pragma unroll
        for (int j = 0; j < 4; j++) {
            float lo, hi;
            upk2(lo, hi, acc2[i][j]);
            out[r * H1 + tn * 8 + 2 * j + 0] = lo;
            out[r * H1 + tn * 8 + 2 * j + 1] = hi;
        }
    }
}

// ---------------------------------------------------------------------------
// Kernel 2b: phase-A reduction: sum 16 splits per group (1024 blocks).
// ---------------------------------------------------------------------------
__global__ __launch_bounds__(256, 4)
void reduce_kernel()
{
    const int blk = blockIdx.x;          // 0 .. B_DIM*NGRP-1
    const int b = blk >> 4;              // batch row
    const int grp = blk & 15;            // split group
    const int o = threadIdx.x;

    const float* __restrict__ p = g_part + ((long long)grp * SPG * B_DIM + b) * H1 + o;
    float s0 = 0.f, s1 = 0.f, s2 = 0.f, s3 = 0.f;
#pragma unroll
    for (int s = 0; s < SPG; s += 4) {
        s0 += p[(long long)(s + 0) * (B_DIM * H1)];
        s1 += p[(long long)(s + 1) * (B_DIM * H1)];
        s2 += p[(long long)(s + 2) * (B_DIM * H1)];
        s3 += p[(long long)(s + 3) * (B_DIM * H1)];
    }
    g_part2[((long long)grp * B_DIM + b) * H1 + o] = (s0 + s1) + (s2 + s3);
}

// ---------------------------------------------------------------------------
// Kernel 3: final reduce (16 groups) + bias/relu + layers 2/3 + softmax.
// ---------------------------------------------------------------------------
__global__ __launch_bounds__(256, 1)
void mlp_kernel(const float* __restrict__ b1,
                const float* __restrict__ W2,
                const float* __restrict__ b2,
                const float* __restrict__ W3,
                const float* __restrict__ b3,
                float* __restrict__ out)
{
    __shared__ float sv[H1];
    __shared__ float s2[H2];
    __shared__ float sl[NCLS];

    const int b = blockIdx.x;
    const int o = threadIdx.x;

    const float* __restrict__ p = g_part2 + (long long)b * H1 + o;
    float s0 = 0.f, s1 = 0.f, s2a = 0.f, s3 = 0.f;
#pragma unroll
    for (int s = 0; s < NGRP; s += 4) {
        s0  += p[(long long)(s + 0) * (B_DIM * H1)];
        s1  += p[(long long)(s + 1) * (B_DIM * H1)];
        s2a += p[(long long)(s + 2) * (B_DIM * H1)];
        s3  += p[(long long)(s + 3) * (B_DIM * H1)];
    }
    float v = b1[o] + ((s0 + s1) + (s2a + s3));
    sv[o] = fmaxf(v, 0.0f);
    __syncthreads();

    if (o < H2) {
        float a = b2[o];
#pragma unroll 8
        for (int i = 0; i < H1; i++)
            a = fmaf(sv[i], W2[i * H2 + o], a);
        s2[o] = fmaxf(a, 0.0f);
    }
    __syncthreads();

    if (o < NCLS) {
        float a = b3[o];
#pragma unroll
        for (int j = 0; j < H2; j++)
            a = fmaf(s2[j], W3[j * NCLS + o], a);
        sl[o] = a;
    }
    __syncthreads();

    if (o == 0) {
        float mx = fmaxf(sl[0], sl[1]);
        float e0 = __expf(sl[0] - mx);
        float e1 = __expf(sl[1] - mx);
        float inv = __fdividef(1.0f, e0 + e1);
        out[b * NCLS + 0] = e0 * inv;
        out[b * NCLS + 1] = e1 * inv;
    }
}

// ---------------------------------------------------------------------------
extern "C" void kernel_launch(void* const* d_in, const int* in_sizes, int n_in,
                              void* d_out, int out_size)
{
    const float* inputs = (const float*)d_in[0];
    const float* Wn = (const float*)d_in[1];
    const float* Wg = (const float*)d_in[2];
    const float* Ug = (const float*)d_in[3];
    const float* bg = (const float*)d_in[4];
    const float* Wc = (const float*)d_in[5];
    const float* Uc = (const float*)d_in[6];
    const float* bc = (const float*)d_in[7];
    const float* We = (const float*)d_in[8];
    const float* be = (const float*)d_in[9];
    const float* W1 = (const float*)d_in[10];
    const float* b1 = (const float*)d_in[11];
    const float* W2 = (const float*)d_in[12];
    const float* b2 = (const float*)d_in[13];
    const float* W3 = (const float*)d_in[14];
    const float* b3 = (const float*)d_in[15];
    float* out = (float*)d_out;

    // async D2D copies into constant bank (graph-capturable)
    cudaMemcpyToSymbolAsync(cWn, Wn, K_DIM * U_DIM * sizeof(float), 0, cudaMemcpyDeviceToDevice, 0);
    cudaMemcpyToSymbolAsync(cWg, Wg, U_DIM * U_DIM * sizeof(float), 0, cudaMemcpyDeviceToDevice, 0);
    cudaMemcpyToSymbolAsync(cUg, Ug, U_DIM * U_DIM * sizeof(float), 0, cudaMemcpyDeviceToDevice, 0);
    cudaMemcpyToSymbolAsync(cWc, Wc, U_DIM * U_DIM * sizeof(float), 0, cudaMemcpyDeviceToDevice, 0);
    cudaMemcpyToSymbolAsync(cUc, Uc, U_DIM * U_DIM * sizeof(float), 0, cudaMemcpyDeviceToDevice, 0);
    cudaMemcpyToSymbolAsync(cWe, We, U_DIM * U_DIM * sizeof(float), 0, cudaMemcpyDeviceToDevice, 0);
    cudaMemcpyToSymbolAsync(cb, bg, U_DIM * sizeof(float), 0 * U_DIM * sizeof(float), cudaMemcpyDeviceToDevice, 0);
    cudaMemcpyToSymbolAsync(cb, bc, U_DIM * sizeof(float), 1 * U_DIM * sizeof(float), cudaMemcpyDeviceToDevice, 0);
    cudaMemcpyToSymbolAsync(cb, be, U_DIM * sizeof(float), 2 * U_DIM * sizeof(float), cudaMemcpyDeviceToDevice, 0);

    ugrnn_kernel<<<BN / 128, 128>>>(inputs);
    gemm1_kernel<<<NSPLIT, 256>>>(W1);
    reduce_kernel<<<B_DIM * NGRP, 256>>>();
    mlp_kernel<<<B_DIM, 256>>>(b1, W2, b2, W3, b3, out);
}

// round 15
// speedup vs baseline: 10.1274x; 1.1995x over previous
#include <cuda_runtime.h>
#include <math.h>

#define B_DIM 64
#define N_DIM 4096
#define K_DIM 32
#define U_DIM 16
#define NUM_STEPS 8
#define BN (B_DIM * N_DIM)            // 262144 sites
#define NU (N_DIM * U_DIM)            // 65536 (GEMM K)
#define H1 256
#define H2 32
#define NCLS 2
#define ROWLEN (K_DIM + 2)            // 34

#define NSPLIT 256
#define KCHUNK (NU / NSPLIT)          // 256
#define NTILE (KCHUNK / 16)           // 16 k-tiles per split
#define NGRP 16                       // phase-A reduction groups
#define SPG (NSPLIT / NGRP)           // 16 splits per group

// scratch (device globals: allocation-free)
__device__ float g_h[BN * U_DIM];               // 16 MB: h outputs
__device__ float g_part[NSPLIT * B_DIM * H1];   // 16 MB: split-K partials
__device__ float g_part2[NGRP * B_DIM * H1];    // 1 MB: phase-A partials

// weights in constant memory: warp-uniform -> LDCU uniform port
__constant__ __align__(16) float cWn[K_DIM * U_DIM];
__constant__ __align__(16) float cWg[U_DIM * U_DIM];
__constant__ __align__(16) float cUg[U_DIM * U_DIM];
__constant__ __align__(16) float cWc[U_DIM * U_DIM];
__constant__ __align__(16) float cUc[U_DIM * U_DIM];
__constant__ __align__(16) float cWe[U_DIM * U_DIM];
__constant__ __align__(16) float cb[3 * U_DIM];   // bg | bc | be

typedef unsigned long long u64;

// ---- f32x2 helpers (componentwise fp32) ----
__device__ __forceinline__ u64 pk2(float lo, float hi) {
    u64 r;
    asm("mov.b64 %0, {%1, %2};" : "=l"(r) : "f"(lo), "f"(hi));
    return r;
}
__device__ __forceinline__ void upk2(float& lo, float& hi, u64 v) {
    asm("mov.b64 {%0, %1}, %2;" : "=f"(lo), "=f"(hi) : "l"(v));
}
__device__ __forceinline__ u64 ffma2(u64 a, u64 b, u64 c) {
    u64 d;
    asm("fma.rn.f32x2 %0, %1, %2, %3;" : "=l"(d) : "l"(a), "l"(b), "l"(c));
    return d;
}

// ---- HW tanh (MUFU.TANH, sm_75+): 1 MUFU op ----
__device__ __forceinline__ float tanh_hw(float v) {
    float r;
    asm("tanh.approx.f32 %0, %1;" : "=f"(r) : "f"(v));
    return r;
}
__device__ __forceinline__ float sigmoid_hw(float v) {
    // sigmoid(v) = 0.5*tanh(0.5*v) + 0.5
    return fmaf(0.5f, tanh_hw(0.5f * v), 0.5f);
}

// ---------------------------------------------------------------------------
// Kernel 1: UGRNN. 1 thread = 1 site; weights uniform from constant bank.
// Scalar accumulators (f32x2 proved throughput-neutral), HW tanh activations.
// ---------------------------------------------------------------------------
__global__ __launch_bounds__(128, 4)
void ugrnn_kernel(const float* __restrict__ inputs)
{
    const int site = blockIdx.x * 128 + threadIdx.x;   // 0 .. BN-1
    const float* __restrict__ row = inputs + (long long)site * ROWLEN;

    const float h0 = __ldg(&row[0]);
    const float e0 = __ldg(&row[K_DIM + 1]);

    // m[u] = sum_k neigh[k] * Wn[k][u]
    float ms[U_DIM];
#pragma unroll
    for (int u = 0; u < U_DIM; u++) ms[u] = 0.0f;
#pragma unroll 4
    for (int k = 0; k < K_DIM; k++) {
        float nk = __ldg(&row[1 + k]);
#pragma unroll
        for (int u = 0; u < U_DIM; u++)
            ms[u] = fmaf(nk, cWn[k * U_DIM + u], ms[u]);
    }

    float hs[U_DIM], es[U_DIM];
#pragma unroll
    for (int u = 0; u < U_DIM; u++) { hs[u] = h0; es[u] = e0; }

#pragma unroll 1
    for (int step = 0; step < NUM_STEPS; step++) {
        // x = m + e, in place into es (es dead until pass 3 rewrites it)
#pragma unroll
        for (int u = 0; u < U_DIM; u++) es[u] = ms[u] + es[u];

        // ---- pass 1: g = sigmoid(x@Wg + h@Ug + bg) ----
        float g[U_DIM];
        {
            float acc[U_DIM];
#pragma unroll
            for (int u = 0; u < U_DIM; u++) acc[u] = cb[u];
#pragma unroll
            for (int j = 0; j < U_DIM; j++) {
                const float xj = es[j];
                const float hj = hs[j];
#pragma unroll
                for (int u = 0; u < U_DIM; u++)
                    acc[u] = fmaf(xj, cWg[j * U_DIM + u],
                             fmaf(hj, cUg[j * U_DIM + u], acc[u]));
            }
#pragma unroll
            for (int u = 0; u < U_DIM; u++) g[u] = sigmoid_hw(acc[u]);
        }

        // ---- pass 2: c = tanh(x@Wc + h@Uc + bc); h = g*h + (1-g)*c ----
        {
            float acc[U_DIM];
#pragma unroll
            for (int u = 0; u < U_DIM; u++) acc[u] = cb[U_DIM + u];
#pragma unroll
            for (int j = 0; j < U_DIM; j++) {
                const float xj = es[j];
                const float hj = hs[j];
#pragma unroll
                for (int u = 0; u < U_DIM; u++)
                    acc[u] = fmaf(xj, cWc[j * U_DIM + u],
                             fmaf(hj, cUc[j * U_DIM + u], acc[u]));
            }
#pragma unroll
            for (int u = 0; u < U_DIM; u++) {
                float c = tanh_hw(acc[u]);
                hs[u] = fmaf(g[u], hs[u] - c, c);   // g*h + (1-g)*c
            }
        }

        // ---- pass 3: e = tanh(x@We + be)  (skip on last step: unused) ----
        if (step < NUM_STEPS - 1) {
            float acc[U_DIM];
#pragma unroll
            for (int u = 0; u < U_DIM; u++) acc[u] = cb[2 * U_DIM + u];
#pragma unroll
            for (int j = 0; j < U_DIM; j++) {
                const float xj = es[j];
#pragma unroll
                for (int u = 0; u < U_DIM; u++)
                    acc[u] = fmaf(xj, cWe[j * U_DIM + u], acc[u]);
            }
#pragma unroll
            for (int u = 0; u < U_DIM; u++) es[u] = tanh_hw(acc[u]);
        }
    }

    float* __restrict__ dst = g_h + (long long)site * U_DIM;
#pragma unroll
    for (int q = 0; q < 4; q++) {
        float4 v = make_float4(hs[q * 4 + 0], hs[q * 4 + 1], hs[q * 4 + 2], hs[q * 4 + 3]);
        *(float4*)&dst[q * 4] = v;
    }
}

// ---------------------------------------------------------------------------
// Kernel 2: split-K GEMM, DOUBLE-BUFFERED smem + reg prefetch.
// part[split] = A(64 x KCHUNK) * W1(KCHUNK x 256)
// ---------------------------------------------------------------------------
__global__ __launch_bounds__(256, 2)
void gemm1_kernel(const float* __restrict__ W1)
{
    __shared__ __align__(16) float As[2][16][B_DIM];     // 2 x 4 KB
    __shared__ __align__(16) float Bs[2][16][H1];        // 2 x 16 KB

    const int split = blockIdx.x;
    const int k0 = split * KCHUNK;
    const int tid = threadIdx.x;
    const int tm = tid >> 5;            // 0..7
    const int tn = tid & 31;            // 0..31

    u64 acc2[8][4];
#pragma unroll
    for (int i = 0; i < 8; i++)
#pragma unroll
        for (int j = 0; j < 4; j++) acc2[i][j] = 0ull;

    const int ar = tid >> 2;             // row 0..63
    const int akq = (tid & 3) * 4;       // k offset 0,4,8,12
    const int bkr = tid >> 6;            // 0..3   (B row base; +4 per i)
    const int bcq = (tid & 63) * 4;      // col 0..252

    // prologue: load tile 0 -> regs -> smem buf 0
    float4 avp = *(const float4*)&g_h[(long long)ar * NU + k0 + akq];
    float4 bvp[4];
#pragma unroll
    for (int i = 0; i < 4; i++)
        bvp[i] = *(const float4*)&W1[(long long)(k0 + bkr + i * 4) * H1 + bcq];

    As[0][akq + 0][ar] = avp.x;
    As[0][akq + 1][ar] = avp.y;
    As[0][akq + 2][ar] = avp.z;
    As[0][akq + 3][ar] = avp.w;
#pragma unroll
    for (int i = 0; i < 4; i++)
        *(float4*)&Bs[0][bkr + i * 4][bcq] = bvp[i];
    __syncthreads();

#pragma unroll 1
    for (int t = 0; t < NTILE; t++) {
        const int cur = t & 1;
        // prefetch next tile into regs (latency hidden by compute below)
        if (t + 1 < NTILE) {
            const int kk = (t + 1) * 16;
            avp = *(const float4*)&g_h[(long long)ar * NU + k0 + kk + akq];
#pragma unroll
            for (int i = 0; i < 4; i++)
                bvp[i] = *(const float4*)&W1[(long long)(k0 + kk + bkr + i * 4) * H1 + bcq];
        }

        // compute current tile
#pragma unroll
        for (int k = 0; k < 16; k++) {
            float a[8];
            float4 a0 = *(const float4*)&As[cur][k][tm * 8];
            float4 a1 = *(const float4*)&As[cur][k][tm * 8 + 4];
            a[0] = a0.x; a[1] = a0.y; a[2] = a0.z; a[3] = a0.w;
            a[4] = a1.x; a[5] = a1.y; a[6] = a1.z; a[7] = a1.w;
            u64 b2[4];
            {
                const ulonglong2* bp = (const ulonglong2*)&Bs[cur][k][tn * 8];
                ulonglong2 q0 = bp[0];
                ulonglong2 q1 = bp[1];
                b2[0] = q0.x; b2[1] = q0.y; b2[2] = q1.x; b2[3] = q1.y;
            }
#pragma unroll
            for (int i = 0; i < 8; i++) {
                u64 a2 = pk2(a[i], a[i]);
#pragma unroll
                for (int j = 0; j < 4; j++)
                    acc2[i][j] = ffma2(a2, b2[j], acc2[i][j]);
            }
        }

        // stage next tile into the other buffer
        if (t + 1 < NTILE) {
            const int nxt = cur ^ 1;
            As[nxt][akq + 0][ar] = avp.x;
            As[nxt][akq + 1][ar] = avp.y;
            As[nxt][akq + 2][ar] = avp.z;
            As[nxt][akq + 3][ar] = avp.w;
#pragma unroll
            for (int i = 0; i < 4; i++)
                *(float4*)&Bs[nxt][bkr + i * 4][bcq] = bvp[i];
            __syncthreads();
        }
    }

    float* __restrict__ out = g_part + (long long)split * (B_DIM * H1);
#pragma unroll
    for (int i = 0; i < 8; i++) {
        int r = tm * 8 + i;
#pragma unroll
        for (int j = 0; j < 4; j++) {
            float lo, hi;
            upk2(lo, hi, acc2[i][j]);
            out[r * H1 + tn * 8 + 2 * j + 0] = lo;
            out[r * H1 + tn * 8 + 2 * j + 1] = hi;
        }
    }
}

// ---------------------------------------------------------------------------
// Kernel 2b: phase-A reduction: sum 16 splits per group (1024 blocks).
// ---------------------------------------------------------------------------
__global__ __launch_bounds__(256, 4)
void reduce_kernel()
{
    const int blk = blockIdx.x;          // 0 .. B_DIM*NGRP-1
    const int b = blk >> 4;              // batch row
    const int grp = blk & 15;            // split group
    const int o = threadIdx.x;

    const float* __restrict__ p = g_part + ((long long)grp * SPG * B_DIM + b) * H1 + o;
    float s0 = 0.f, s1 = 0.f, s2 = 0.f, s3 = 0.f;
#pragma unroll
    for (int s = 0; s < SPG; s += 4) {
        s0 += p[(long long)(s + 0) * (B_DIM * H1)];
        s1 += p[(long long)(s + 1) * (B_DIM * H1)];
        s2 += p[(long long)(s + 2) * (B_DIM * H1)];
        s3 += p[(long long)(s + 3) * (B_DIM * H1)];
    }
    g_part2[((long long)grp * B_DIM + b) * H1 + o] = (s0 + s1) + (s2 + s3);
}

// ---------------------------------------------------------------------------
// Kernel 3: final reduce + bias/relu + layers 2/3 + softmax.
// Layer 2 parallelized: 8 threads per output x 32-element segments.
// ---------------------------------------------------------------------------
__global__ __launch_bounds__(256, 1)
void mlp_kernel(const float* __restrict__ b1,
                const float* __restrict__ W2,
                const float* __restrict__ b2,
                const float* __restrict__ W3,
                const float* __restrict__ b3,
                float* __restrict__ out)
{
    __shared__ float sv[H1];
    __shared__ float spart[8][H2];
    __shared__ float s2[H2];
    __shared__ float sl[NCLS];

    const int b = blockIdx.x;
    const int o = threadIdx.x;

    const float* __restrict__ p = g_part2 + (long long)b * H1 + o;
    float s0 = 0.f, s1 = 0.f, s2a = 0.f, s3 = 0.f;
#pragma unroll
    for (int s = 0; s < NGRP; s += 4) {
        s0  += p[(long long)(s + 0) * (B_DIM * H1)];
        s1  += p[(long long)(s + 1) * (B_DIM * H1)];
        s2a += p[(long long)(s + 2) * (B_DIM * H1)];
        s3  += p[(long long)(s + 3) * (B_DIM * H1)];
    }
    float v = b1[o] + ((s0 + s1) + (s2a + s3));
    sv[o] = fmaxf(v, 0.0f);
    __syncthreads();

    // layer 2: out col = o & 31, segment = o >> 5 (rows seg*32 .. seg*32+31)
    {
        const int col = o & 31;
        const int seg = o >> 5;
        float a = 0.0f;
#pragma unroll 8
        for (int i = 0; i < 32; i++) {
            int r = seg * 32 + i;
            a = fmaf(sv[r], __ldg(&W2[r * H2 + col]), a);
        }
        spart[seg][col] = a;
    }
    __syncthreads();

    if (o < H2) {
        float a = b2[o];
#pragma unroll
        for (int s = 0; s < 8; s++) a += spart[s][o];
        s2[o] = fmaxf(a, 0.0f);
    }
    __syncthreads();

    if (o < NCLS) {
        float a = b3[o];
#pragma unroll
        for (int j = 0; j < H2; j++)
            a = fmaf(s2[j], W3[j * NCLS + o], a);
        sl[o] = a;
    }
    __syncthreads();

    if (o == 0) {
        float mx = fmaxf(sl[0], sl[1]);
        float e0 = __expf(sl[0] - mx);
        float e1 = __expf(sl[1] - mx);
        float inv = __fdividef(1.0f, e0 + e1);
        out[b * NCLS + 0] = e0 * inv;
        out[b * NCLS + 1] = e1 * inv;
    }
}

// ---------------------------------------------------------------------------
extern "C" void kernel_launch(void* const* d_in, const int* in_sizes, int n_in,
                              void* d_out, int out_size)
{
    const float* inputs = (const float*)d_in[0];
    const float* Wn = (const float*)d_in[1];
    const float* Wg = (const float*)d_in[2];
    const float* Ug = (const float*)d_in[3];
    const float* bg = (const float*)d_in[4];
    const float* Wc = (const float*)d_in[5];
    const float* Uc = (const float*)d_in[6];
    const float* bc = (const float*)d_in[7];
    const float* We = (const float*)d_in[8];
    const float* be = (const float*)d_in[9];
    const float* W1 = (const float*)d_in[10];
    const float* b1 = (const float*)d_in[11];
    const float* W2 = (const float*)d_in[12];
    const float* b2 = (const float*)d_in[13];
    const float* W3 = (const float*)d_in[14];
    const float* b3 = (const float*)d_in[15];
    float* out = (float*)d_out;

    // async D2D copies into constant bank (graph-capturable)
    cudaMemcpyToSymbolAsync(cWn, Wn, K_DIM * U_DIM * sizeof(float), 0, cudaMemcpyDeviceToDevice, 0);
    cudaMemcpyToSymbolAsync(cWg, Wg, U_DIM * U_DIM * sizeof(float), 0, cudaMemcpyDeviceToDevice, 0);
    cudaMemcpyToSymbolAsync(cUg, Ug, U_DIM * U_DIM * sizeof(float), 0, cudaMemcpyDeviceToDevice, 0);
    cudaMemcpyToSymbolAsync(cWc, Wc, U_DIM * U_DIM * sizeof(float), 0, cudaMemcpyDeviceToDevice, 0);
    cudaMemcpyToSymbolAsync(cUc, Uc, U_DIM * U_DIM * sizeof(float), 0, cudaMemcpyDeviceToDevice, 0);
    cudaMemcpyToSymbolAsync(cWe, We, U_DIM * U_DIM * sizeof(float), 0, cudaMemcpyDeviceToDevice, 0);
    cudaMemcpyToSymbolAsync(cb, bg, U_DIM * sizeof(float), 0 * U_DIM * sizeof(float), cudaMemcpyDeviceToDevice, 0);
    cudaMemcpyToSymbolAsync(cb, bc, U_DIM * sizeof(float), 1 * U_DIM * sizeof(float), cudaMemcpyDeviceToDevice, 0);
    cudaMemcpyToSymbolAsync(cb, be, U_DIM * sizeof(float), 2 * U_DIM * sizeof(float), cudaMemcpyDeviceToDevice, 0);

    ugrnn_kernel<<<BN / 128, 128>>>(inputs);
    gemm1_kernel<<<NSPLIT, 256>>>(W1);
    reduce_kernel<<<B_DIM * NGRP, 256>>>();
    mlp_kernel<<<B_DIM, 256>>>(b1, W2, b2, W3, b3, out);
}

// round 16
// speedup vs baseline: 10.6674x; 1.0533x over previous
#include <cuda_runtime.h>
#include <cuda_bf16.h>
#include <math.h>

#define B_DIM 64
#define N_DIM 4096
#define K_DIM 32
#define U_DIM 16
#define NUM_STEPS 8
#define BN (B_DIM * N_DIM)            // 262144 sites
#define NU (N_DIM * U_DIM)            // 65536 (GEMM K)
#define H1 256
#define H2 32
#define NCLS 2
#define ROWLEN (K_DIM + 2)            // 34

#define NSPLIT 256
#define KCHUNK (NU / NSPLIT)          // 256
#define NTILE (KCHUNK / 16)           // 16 k-tiles per split
#define NGRP 16                       // phase-A reduction groups
#define SPG (NSPLIT / NGRP)           // 16 splits per group

// scratch (device globals: allocation-free)
__device__ float g_h[BN * U_DIM];               // 16 MB: h outputs
__device__ float g_part[NSPLIT * B_DIM * H1];   // 16 MB: split-K partials
__device__ float g_part2[NGRP * B_DIM * H1];    // 1 MB: phase-A partials

// weights in constant memory: warp-uniform -> uniform const port
__constant__ __align__(16) float cWn[K_DIM * U_DIM];
__constant__ __align__(16) float cWg[U_DIM * U_DIM];
__constant__ __align__(16) float cUg[U_DIM * U_DIM];
__constant__ __align__(16) float cWc[U_DIM * U_DIM];
__constant__ __align__(16) float cUc[U_DIM * U_DIM];
__constant__ __align__(16) float cWe[U_DIM * U_DIM];
__constant__ __align__(16) float cb[3 * U_DIM];   // bg | bc | be

// ---- HW tanh (MUFU.TANH) ----
__device__ __forceinline__ float tanh_hw(float v) {
    float r;
    asm("tanh.approx.f32 %0, %1;" : "=f"(r) : "f"(v));
    return r;
}
__device__ __forceinline__ float sigmoid_hw(float v) {
    return fmaf(0.5f, tanh_hw(0.5f * v), 0.5f);
}

// ---- bf16 mma.sync m16n8k16 ----
__device__ __forceinline__ void mma_bf16(float* d, const unsigned* a, const unsigned* b) {
    asm volatile("mma.sync.aligned.m16n8k16.row.col.f32.bf16.bf16.f32 "
        "{%0,%1,%2,%3}, {%4,%5,%6,%7}, {%8,%9}, {%0,%1,%2,%3};"
        : "+f"(d[0]), "+f"(d[1]), "+f"(d[2]), "+f"(d[3])
        : "r"(a[0]), "r"(a[1]), "r"(a[2]), "r"(a[3]), "r"(b[0]), "r"(b[1]));
}

// ---------------------------------------------------------------------------
// Kernel 1: UGRNN (unchanged from R15 — at its FMA-pipe floor).
// ---------------------------------------------------------------------------
__global__ __launch_bounds__(128, 4)
void ugrnn_kernel(const float* __restrict__ inputs)
{
    const int site = blockIdx.x * 128 + threadIdx.x;
    const float* __restrict__ row = inputs + (long long)site * ROWLEN;

    const float h0 = __ldg(&row[0]);
    const float e0 = __ldg(&row[K_DIM + 1]);

    float ms[U_DIM];
#pragma unroll
    for (int u = 0; u < U_DIM; u++) ms[u] = 0.0f;
#pragma unroll 4
    for (int k = 0; k < K_DIM; k++) {
        float nk = __ldg(&row[1 + k]);
#pragma unroll
        for (int u = 0; u < U_DIM; u++)
            ms[u] = fmaf(nk, cWn[k * U_DIM + u], ms[u]);
    }

    float hs[U_DIM], es[U_DIM];
#pragma unroll
    for (int u = 0; u < U_DIM; u++) { hs[u] = h0; es[u] = e0; }

#pragma unroll 1
    for (int step = 0; step < NUM_STEPS; step++) {
#pragma unroll
        for (int u = 0; u < U_DIM; u++) es[u] = ms[u] + es[u];

        float g[U_DIM];
        {
            float acc[U_DIM];
#pragma unroll
            for (int u = 0; u < U_DIM; u++) acc[u] = cb[u];
#pragma unroll
            for (int j = 0; j < U_DIM; j++) {
                const float xj = es[j];
                const float hj = hs[j];
#pragma unroll
                for (int u = 0; u < U_DIM; u++)
                    acc[u] = fmaf(xj, cWg[j * U_DIM + u],
                             fmaf(hj, cUg[j * U_DIM + u], acc[u]));
            }
#pragma unroll
            for (int u = 0; u < U_DIM; u++) g[u] = sigmoid_hw(acc[u]);
        }

        {
            float acc[U_DIM];
#pragma unroll
            for (int u = 0; u < U_DIM; u++) acc[u] = cb[U_DIM + u];
#pragma unroll
            for (int j = 0; j < U_DIM; j++) {
                const float xj = es[j];
                const float hj = hs[j];
#pragma unroll
                for (int u = 0; u < U_DIM; u++)
                    acc[u] = fmaf(xj, cWc[j * U_DIM + u],
                             fmaf(hj, cUc[j * U_DIM + u], acc[u]));
            }
#pragma unroll
            for (int u = 0; u < U_DIM; u++) {
                float c = tanh_hw(acc[u]);
                hs[u] = fmaf(g[u], hs[u] - c, c);
            }
        }

        if (step < NUM_STEPS - 1) {
            float acc[U_DIM];
#pragma unroll
            for (int u = 0; u < U_DIM; u++) acc[u] = cb[2 * U_DIM + u];
#pragma unroll
            for (int j = 0; j < U_DIM; j++) {
                const float xj = es[j];
#pragma unroll
                for (int u = 0; u < U_DIM; u++)
                    acc[u] = fmaf(xj, cWe[j * U_DIM + u], acc[u]);
            }
#pragma unroll
            for (int u = 0; u < U_DIM; u++) es[u] = tanh_hw(acc[u]);
        }
    }

    float* __restrict__ dst = g_h + (long long)site * U_DIM;
#pragma unroll
    for (int q = 0; q < 4; q++) {
        float4 v = make_float4(hs[q * 4 + 0], hs[q * 4 + 1], hs[q * 4 + 2], hs[q * 4 + 3]);
        *(float4*)&dst[q * 4] = v;
    }
}

// ---------------------------------------------------------------------------
// Kernel 2: split-K GEMM on tensor cores: bf16 3-term hi/lo split.
// part[split] = A(64 x 256) * W1(256 x 256), A from g_h.
// 8 warps: warp w owns output m64 x n[32w..32w+32).
// ---------------------------------------------------------------------------
__global__ __launch_bounds__(256, 2)
void gemm1_kernel(const float* __restrict__ W1)
{
    __shared__ __nv_bfloat16 sAhi[2][B_DIM][16];    // 2 x 2 KB
    __shared__ __nv_bfloat16 sAlo[2][B_DIM][16];
    __shared__ __nv_bfloat16 sBhi[2][H1][16];       // 2 x 8 KB
    __shared__ __nv_bfloat16 sBlo[2][H1][16];

    const int split = blockIdx.x;
    const int k0 = split * KCHUNK;
    const int tid = threadIdx.x;
    const int warp = tid >> 5;
    const int lane = tid & 31;
    const int qp = lane >> 2;       // 0..7
    const int rp = lane & 3;        // 0..3
    const int warpN = warp * 32;

    float acc[4][4][4];             // [m-tile][n-tile][frag]
#pragma unroll
    for (int i = 0; i < 4; i++)
#pragma unroll
        for (int j = 0; j < 4; j++)
#pragma unroll
            for (int q = 0; q < 4; q++) acc[i][j][q] = 0.0f;

    // staging indices
    const int a_b = (tid >> 4);          // base row for A loads (rep adds 16)
    const int a_k = tid & 15;            // k within tile

    float pa[4], pb[16];

    // ---- prologue: tile 0 ----
#pragma unroll
    for (int r = 0; r < 4; r++)
        pa[r] = g_h[(long long)(r * 16 + a_b) * NU + k0 + a_k];
#pragma unroll
    for (int r = 0; r < 16; r++)
        pb[r] = W1[(long long)(k0 + r) * H1 + tid];

    {
#pragma unroll
        for (int r = 0; r < 4; r++) {
            __nv_bfloat16 h = __float2bfloat16_rn(pa[r]);
            sAhi[0][r * 16 + a_b][a_k] = h;
            sAlo[0][r * 16 + a_b][a_k] = __float2bfloat16_rn(pa[r] - __bfloat162float(h));
        }
#pragma unroll
        for (int r = 0; r < 16; r++) {
            __nv_bfloat16 h = __float2bfloat16_rn(pb[r]);
            sBhi[0][tid][r] = h;
            sBlo[0][tid][r] = __float2bfloat16_rn(pb[r] - __bfloat162float(h));
        }
    }
    __syncthreads();

#pragma unroll 1
    for (int t = 0; t < NTILE; t++) {
        const int cur = t & 1;

        // prefetch next tile into regs
        if (t + 1 < NTILE) {
            const int kk = (t + 1) * 16;
#pragma unroll
            for (int r = 0; r < 4; r++)
                pa[r] = g_h[(long long)(r * 16 + a_b) * NU + k0 + kk + a_k];
#pragma unroll
            for (int r = 0; r < 16; r++)
                pb[r] = W1[(long long)(k0 + kk + r) * H1 + tid];
        }

        // B fragments for this warp's 4 n-tiles
        unsigned bhi[4][2], blo[4][2];
#pragma unroll
        for (int nt = 0; nt < 4; nt++) {
            const int n = warpN + nt * 8 + qp;
            bhi[nt][0] = *(const unsigned*)&sBhi[cur][n][rp * 2];
            bhi[nt][1] = *(const unsigned*)&sBhi[cur][n][rp * 2 + 8];
            blo[nt][0] = *(const unsigned*)&sBlo[cur][n][rp * 2];
            blo[nt][1] = *(const unsigned*)&sBlo[cur][n][rp * 2 + 8];
        }

        // m-tiles: load A frags, run 3-term MMAs
#pragma unroll
        for (int mt = 0; mt < 4; mt++) {
            const int r0 = mt * 16 + qp;
            unsigned ahi[4], alo[4];
            ahi[0] = *(const unsigned*)&sAhi[cur][r0][rp * 2];
            ahi[1] = *(const unsigned*)&sAhi[cur][r0 + 8][rp * 2];
            ahi[2] = *(const unsigned*)&sAhi[cur][r0][rp * 2 + 8];
            ahi[3] = *(const unsigned*)&sAhi[cur][r0 + 8][rp * 2 + 8];
            alo[0] = *(const unsigned*)&sAlo[cur][r0][rp * 2];
            alo[1] = *(const unsigned*)&sAlo[cur][r0 + 8][rp * 2];
            alo[2] = *(const unsigned*)&sAlo[cur][r0][rp * 2 + 8];
            alo[3] = *(const unsigned*)&sAlo[cur][r0 + 8][rp * 2 + 8];
#pragma unroll
            for (int nt = 0; nt < 4; nt++) {
                mma_bf16(acc[mt][nt], ahi, bhi[nt]);
                mma_bf16(acc[mt][nt], ahi, blo[nt]);
                mma_bf16(acc[mt][nt], alo, bhi[nt]);
            }
        }

        // stage next tile
        if (t + 1 < NTILE) {
            const int nxt = cur ^ 1;
#pragma unroll
            for (int r = 0; r < 4; r++) {
                __nv_bfloat16 h = __float2bfloat16_rn(pa[r]);
                sAhi[nxt][r * 16 + a_b][a_k] = h;
                sAlo[nxt][r * 16 + a_b][a_k] = __float2bfloat16_rn(pa[r] - __bfloat162float(h));
            }
#pragma unroll
            for (int r = 0; r < 16; r++) {
                __nv_bfloat16 h = __float2bfloat16_rn(pb[r]);
                sBhi[nxt][tid][r] = h;
                sBlo[nxt][tid][r] = __float2bfloat16_rn(pb[r] - __bfloat162float(h));
            }
            __syncthreads();
        }
    }

    // epilogue: write D fragments
    float* __restrict__ out = g_part + (long long)split * (B_DIM * H1);
#pragma unroll
    for (int mt = 0; mt < 4; mt++) {
#pragma unroll
        for (int nt = 0; nt < 4; nt++) {
            const int r0 = mt * 16 + qp;
            const int c0 = warpN + nt * 8 + rp * 2;
            *(float2*)&out[r0 * H1 + c0]       = make_float2(acc[mt][nt][0], acc[mt][nt][1]);
            *(float2*)&out[(r0 + 8) * H1 + c0] = make_float2(acc[mt][nt][2], acc[mt][nt][3]);
        }
    }
}

// ---------------------------------------------------------------------------
// Kernel 2b: phase-A reduction: sum 16 splits per group (1024 blocks).
// ---------------------------------------------------------------------------
__global__ __launch_bounds__(256, 4)
void reduce_kernel()
{
    const int blk = blockIdx.x;
    const int b = blk >> 4;
    const int grp = blk & 15;
    const int o = threadIdx.x;

    const float* __restrict__ p = g_part + ((long long)grp * SPG * B_DIM + b) * H1 + o;
    float s0 = 0.f, s1 = 0.f, s2 = 0.f, s3 = 0.f;
#pragma unroll
    for (int s = 0; s < SPG; s += 4) {
        s0 += p[(long long)(s + 0) * (B_DIM * H1)];
        s1 += p[(long long)(s + 1) * (B_DIM * H1)];
        s2 += p[(long long)(s + 2) * (B_DIM * H1)];
        s3 += p[(long long)(s + 3) * (B_DIM * H1)];
    }
    g_part2[((long long)grp * B_DIM + b) * H1 + o] = (s0 + s1) + (s2 + s3);
}

// ---------------------------------------------------------------------------
// Kernel 3: final reduce + bias/relu + layers 2/3 + softmax.
// ---------------------------------------------------------------------------
__global__ __launch_bounds__(256, 1)
void mlp_kernel(const float* __restrict__ b1,
                const float* __restrict__ W2,
                const float* __restrict__ b2,
                const float* __restrict__ W3,
                const float* __restrict__ b3,
                float* __restrict__ out)
{
    __shared__ float sv[H1];
    __shared__ float spart[8][H2];
    __shared__ float s2[H2];
    __shared__ float sl[NCLS];

    const int b = blockIdx.x;
    const int o = threadIdx.x;

    const float* __restrict__ p = g_part2 + (long long)b * H1 + o;
    float s0 = 0.f, s1 = 0.f, s2a = 0.f, s3 = 0.f;
#pragma unroll
    for (int s = 0; s < NGRP; s += 4) {
        s0  += p[(long long)(s + 0) * (B_DIM * H1)];
        s1  += p[(long long)(s + 1) * (B_DIM * H1)];
        s2a += p[(long long)(s + 2) * (B_DIM * H1)];
        s3  += p[(long long)(s + 3) * (B_DIM * H1)];
    }
    float v = b1[o] + ((s0 + s1) + (s2a + s3));
    sv[o] = fmaxf(v, 0.0f);
    __syncthreads();

    {
        const int col = o & 31;
        const int seg = o >> 5;
        float a = 0.0f;
#pragma unroll 8
        for (int i = 0; i < 32; i++) {
            int r = seg * 32 + i;
            a = fmaf(sv[r], __ldg(&W2[r * H2 + col]), a);
        }
        spart[seg][col] = a;
    }
    __syncthreads();

    if (o < H2) {
        float a = b2[o];
#pragma unroll
        for (int s = 0; s < 8; s++) a += spart[s][o];
        s2[o] = fmaxf(a, 0.0f);
    }
    __syncthreads();

    if (o < NCLS) {
        float a = b3[o];
#pragma unroll
        for (int j = 0; j < H2; j++)
            a = fmaf(s2[j], W3[j * NCLS + o], a);
        sl[o] = a;
    }
    __syncthreads();

    if (o == 0) {
        float mx = fmaxf(sl[0], sl[1]);
        float e0 = __expf(sl[0] - mx);
        float e1 = __expf(sl[1] - mx);
        float inv = __fdividef(1.0f, e0 + e1);
        out[b * NCLS + 0] = e0 * inv;
        out[b * NCLS + 1] = e1 * inv;
    }
}

// ---------------------------------------------------------------------------
extern "C" void kernel_launch(void* const* d_in, const int* in_sizes, int n_in,
                              void* d_out, int out_size)
{
    const float* inputs = (const float*)d_in[0];
    const float* Wn = (const float*)d_in[1];
    const float* Wg = (const float*)d_in[2];
    const float* Ug = (const float*)d_in[3];
    const float* bg = (const float*)d_in[4];
    const float* Wc = (const float*)d_in[5];
    const float* Uc = (const float*)d_in[6];
    const float* bc = (const float*)d_in[7];
    const float* We = (const float*)d_in[8];
    const float* be = (const float*)d_in[9];
    const float* W1 = (const float*)d_in[10];
    const float* b1 = (const float*)d_in[11];
    const float* W2 = (const float*)d_in[12];
    const float* b2 = (const float*)d_in[13];
    const float* W3 = (const float*)d_in[14];
    const float* b3 = (const float*)d_in[15];
    float* out = (float*)d_out;

    cudaMemcpyToSymbolAsync(cWn, Wn, K_DIM * U_DIM * sizeof(float), 0, cudaMemcpyDeviceToDevice, 0);
    cudaMemcpyToSymbolAsync(cWg, Wg, U_DIM * U_DIM * sizeof(float), 0, cudaMemcpyDeviceToDevice, 0);
    cudaMemcpyToSymbolAsync(cUg, Ug, U_DIM * U_DIM * sizeof(float), 0, cudaMemcpyDeviceToDevice, 0);
    cudaMemcpyToSymbolAsync(cWc, Wc, U_DIM * U_DIM * sizeof(float), 0, cudaMemcpyDeviceToDevice, 0);
    cudaMemcpyToSymbolAsync(cUc, Uc, U_DIM * U_DIM * sizeof(float), 0, cudaMemcpyDeviceToDevice, 0);
    cudaMemcpyToSymbolAsync(cWe, We, U_DIM * U_DIM * sizeof(float), 0, cudaMemcpyDeviceToDevice, 0);
    cudaMemcpyToSymbolAsync(cb, bg, U_DIM * sizeof(float), 0 * U_DIM * sizeof(float), cudaMemcpyDeviceToDevice, 0);
    cudaMemcpyToSymbolAsync(cb, bc, U_DIM * sizeof(float), 1 * U_DIM * sizeof(float), cudaMemcpyDeviceToDevice, 0);
    cudaMemcpyToSymbolAsync(cb, be, U_DIM * sizeof(float), 2 * U_DIM * sizeof(float), cudaMemcpyDeviceToDevice, 0);

    ugrnn_kernel<<<BN / 128, 128>>>(inputs);
    gemm1_kernel<<<NSPLIT, 256>>>(W1);
    reduce_kernel<<<B_DIM * NGRP, 256>>>();
    mlp_kernel<<<B_DIM, 256>>>(b1, W2, b2, W3, b3, out);
}